// round 2
// baseline (speedup 1.0000x reference)
#include <cuda_runtime.h>

// RITS / BRITS-style recurrent imputation.
// B=256, S=512, F=64, H=128. fp32 throughout.
//
// Parallelization: batch rows are independent except for the scalar loss,
// whose per-step denominator depends only on input m (precomputed).
// One persistent block per 2 batch rows runs all 512 steps; loss partials
// are reduced deterministically at the end.

#define Bdim 256
#define Sdim 512
#define Fdim 64
#define Hdim 128
#define G4   512   // 4*H

// ---- scratch (no allocations allowed) ----
__device__ float g_invDenom[Sdim];
__device__ float g_lossPartial[Bdim / 2];

// ---- shared memory layout (floats) ----
// transposed weight tiles so inner-loop lanes are conflict-free
#define OFF_WTR   0                      // [128][64]  WtrT[k*64+f] = Wtr[f*H+k]
#define OFF_WFR   8192                   // [64][64]   WfrT[k*64+f] = Wfr_m[f][k]
#define OFF_WWC   12288                  // [128][64]  WwcT[k*64+f] = Wwc[f*128+k]
#define OFF_WIHX  20480                  // [64][512]  WihxT[k*512+j] = Wih[j*128+k]
#define OFF_BDH   53248                  // 128
#define OFF_BDM   53376                  // 64
#define OFF_BTR   53440                  // 64
#define OFF_BFR   53504                  // 64
#define OFF_BWC   53568                  // 64
#define OFF_BIO   53632                  // 512 (bih+bhh)
#define OFF_DWDM  54144                  // 64
#define OFF_XL    54208                  // [2][64]
#define OFF_ML    54336
#define OFF_TL    54464
#define OFF_GM    54592
#define OFF_XHAT  54720
#define OFF_XC    54848
#define OFF_ZHAT  54976
#define OFF_BETA  55104
#define OFF_CLC   55232
#define OFF_H     55360                  // [2][128]
#define OFF_GATES 55616                  // [2][512]
#define OFF_RED   56640                  // 256
#define SMEM_FLOATS 56896
#define SMEM_BYTES  (SMEM_FLOATS * 4)    // 227,584 B <= 232,448 opt-in cap

__device__ __forceinline__ float sigf(float v) { return 1.0f / (1.0f + expf(-v)); }

// Precompute per-step 1/(sum(m[:,s,:]) + 1e-5). One block per step, t = batch row.
__global__ void rits_denom_kernel(const float* __restrict__ m) {
    __shared__ float red[256];
    const int s = blockIdx.x;
    const int t = threadIdx.x;
    const float4* p = (const float4*)(m + (size_t)t * Sdim * Fdim + (size_t)s * Fdim);
    float sum = 0.f;
#pragma unroll
    for (int i = 0; i < 16; ++i) { float4 v = p[i]; sum += v.x + v.y + v.z + v.w; }
    red[t] = sum;
    __syncthreads();
    for (int off = 128; off > 0; off >>= 1) {
        if (t < off) red[t] += red[t + off];
        __syncthreads();
    }
    if (t == 0) g_invDenom[s] = 1.0f / (red[0] + 1e-5f);
}

__global__ __launch_bounds__(256, 1) void rits_main_kernel(
    const float* __restrict__ x,   const float* __restrict__ m,   const float* __restrict__ tt,
    const float* __restrict__ Wdh, const float* __restrict__ bdh,
    const float* __restrict__ Wdm, const float* __restrict__ bdm,
    const float* __restrict__ Wtr, const float* __restrict__ btr,
    const float* __restrict__ Wfr, const float* __restrict__ bfr,
    const float* __restrict__ Wwc, const float* __restrict__ bwc,
    const float* __restrict__ Wih, const float* __restrict__ Whh,
    const float* __restrict__ bih, const float* __restrict__ bhh,
    float* __restrict__ out)
{
    extern __shared__ float sm[];
    const int t  = threadIdx.x;
    const int b0 = blockIdx.x * 2;

    // ---- one-time weight staging (transposed into smem) ----
    for (int i = t; i < 8192; i += 256) { int k = i >> 6, f = i & 63; sm[OFF_WTR + i] = Wtr[f * Hdim + k]; }
    for (int i = t; i < 4096; i += 256) { int k = i >> 6, f = i & 63; sm[OFF_WFR + i] = (k == f) ? 0.f : Wfr[f * Fdim + k]; }
    for (int i = t; i < 8192; i += 256) { int k = i >> 6, f = i & 63; sm[OFF_WWC + i] = Wwc[f * 2 * Fdim + k]; }
    for (int i = t; i < 32768; i += 256) { int k = i >> 9, j = i & 511; sm[OFF_WIHX + i] = Wih[j * 2 * Fdim + k]; }
    if (t < 128) sm[OFF_BDH + t] = bdh[t];
    if (t < 64) {
        sm[OFF_BDM + t] = bdm[t];
        sm[OFF_BTR + t] = btr[t];
        sm[OFF_BFR + t] = bfr[t];
        sm[OFF_BWC + t] = bwc[t];
        sm[OFF_DWDM + t] = Wdm[t * Fdim + t];   // diagonal of Wdm
    }
    for (int i = t; i < 512; i += 256) sm[OFF_BIO + i] = bih[i] + bhh[i];
    sm[OFF_H + t] = 0.f;                        // h[2][128] zero
    float c_reg   = 0.f;                        // c for (g = t>>7, j = t&127)
    float loss_acc = 0.f;
    __syncthreads();

    for (int s = 0; s < Sdim; ++s) {
        // ---- Phase A: load x,m,t slice; gamma_m ----
        if (t < 128) {
            const int g = t >> 6, f = t & 63;
            const size_t idx = (size_t)(b0 + g) * Sdim * Fdim + (size_t)s * Fdim + f;
            const float xv = x[idx], mv = m[idx], tv = tt[idx];
            sm[OFF_XL + t] = xv;
            sm[OFF_ML + t] = mv;
            sm[OFF_TL + t] = tv;
            sm[OFF_GM + t] = expf(-fmaxf(tv * sm[OFF_DWDM + f] + sm[OFF_BDM + f], 0.f));
        }
        __syncthreads();

        // ---- Phase B: gamma_h, decay h (thread j handles both batch rows) ----
        if (t < 128) {
            const float4* wrow = (const float4*)(Wdh + t * Fdim);
            float a0 = 0.f, a1 = 0.f;
#pragma unroll
            for (int kk = 0; kk < 16; ++kk) {
                const float4 w = wrow[kk];
                const int k = kk * 4;
                a0 += w.x * sm[OFF_TL + k]     + w.y * sm[OFF_TL + k + 1]
                    + w.z * sm[OFF_TL + k + 2] + w.w * sm[OFF_TL + k + 3];
                a1 += w.x * sm[OFF_TL + 64 + k]     + w.y * sm[OFF_TL + 64 + k + 1]
                    + w.z * sm[OFF_TL + 64 + k + 2] + w.w * sm[OFF_TL + 64 + k + 3];
            }
            const float b = sm[OFF_BDH + t];
            sm[OFF_H + t]       *= expf(-fmaxf(a0 + b, 0.f));
            sm[OFF_H + 128 + t] *= expf(-fmaxf(a1 + b, 0.f));
        }
        __syncthreads();

        // ---- Phase C: xl_hat, xl_c ----
        if (t < 128) {
            const int g = t >> 6, f = t & 63;
            const float* hg = sm + OFF_H + g * 128;
            float a = sm[OFF_BTR + f];
#pragma unroll 8
            for (int k = 0; k < 128; ++k) a += hg[k] * sm[OFF_WTR + k * 64 + f];
            sm[OFF_XHAT + t] = a;
            const float mv = sm[OFF_ML + t];
            sm[OFF_XC + t] = mv * sm[OFF_XL + t] + (1.f - mv) * a;
        }
        __syncthreads();

        // ---- Phase D: zl_hat (threads 0..127) | beta (threads 128..255) ----
        if (t < 128) {
            const int g = t >> 6, f = t & 63;
            const float* xcg = sm + OFF_XC + g * 64;
            float a = sm[OFF_BFR + f];
#pragma unroll 8
            for (int k = 0; k < 64; ++k) a += xcg[k] * sm[OFF_WFR + k * 64 + f];
            sm[OFF_ZHAT + t] = a;
        } else {
            const int u = t - 128;
            const int g = u >> 6, f = u & 63;
            const float* gmg = sm + OFF_GM + g * 64;
            const float* mlg = sm + OFF_ML + g * 64;
            float a = sm[OFF_BWC + f];
#pragma unroll 8
            for (int k = 0; k < 64; ++k) {
                a += gmg[k] * sm[OFF_WWC + k * 64 + f];
                a += mlg[k] * sm[OFF_WWC + (64 + k) * 64 + f];
            }
            sm[OFF_BETA + u] = a;
        }
        __syncthreads();

        // ---- Phase E: cl_hat, cl_c, imputation write, loss ----
        if (t < 128) {
            const int g = t >> 6, f = t & 63;
            const float bt = sm[OFF_BETA + t], zh = sm[OFF_ZHAT + t];
            const float xh = sm[OFF_XHAT + t], mv = sm[OFF_ML + t], xv = sm[OFF_XL + t];
            const float ch = bt * zh + (1.f - bt) * xh;
            const float cc = mv * xv + (1.f - mv) * ch;
            sm[OFF_CLC + t] = cc;
            out[(size_t)(b0 + g) * Sdim * Fdim + (size_t)s * Fdim + f] = cc;
            const float d1 = xv - xh, d2 = xv - zh, d3 = xv - ch;
            loss_acc += mv * (d1 * d1 + d2 * d2 + d3 * d3) * g_invDenom[s];
        }
        __syncthreads();

        // ---- Phase F: gates = [cl_c, ml]@Wih^T + h@Whh^T + (bih+bhh) ----
        {
            const int j0 = t, j1 = t + 256;
            float a0g0 = sm[OFF_BIO + j0], a0g1 = a0g0;
            float a1g0 = sm[OFF_BIO + j1], a1g1 = a1g0;
            // cl_c half of Wih from smem
#pragma unroll 8
            for (int k = 0; k < 64; ++k) {
                const float c0 = sm[OFF_CLC + k], c1 = sm[OFF_CLC + 64 + k];
                const float w0 = sm[OFF_WIHX + k * 512 + j0];
                const float w1 = sm[OFF_WIHX + k * 512 + j1];
                a0g0 += w0 * c0; a0g1 += w0 * c1;
                a1g0 += w1 * c0; a1g1 += w1 * c1;
            }
            // mask half of Wih from L2
            const float4* w0p = (const float4*)(Wih + j0 * 128 + 64);
            const float4* w1p = (const float4*)(Wih + j1 * 128 + 64);
#pragma unroll
            for (int kk = 0; kk < 16; ++kk) {
                const float4 w0 = w0p[kk], w1 = w1p[kk];
                const int k = kk * 4;
                const float m00 = sm[OFF_ML + k],     m01 = sm[OFF_ML + k + 1];
                const float m02 = sm[OFF_ML + k + 2], m03 = sm[OFF_ML + k + 3];
                const float m10 = sm[OFF_ML + 64 + k],     m11 = sm[OFF_ML + 64 + k + 1];
                const float m12 = sm[OFF_ML + 64 + k + 2], m13 = sm[OFF_ML + 64 + k + 3];
                a0g0 += w0.x * m00 + w0.y * m01 + w0.z * m02 + w0.w * m03;
                a0g1 += w0.x * m10 + w0.y * m11 + w0.z * m12 + w0.w * m13;
                a1g0 += w1.x * m00 + w1.y * m01 + w1.z * m02 + w1.w * m03;
                a1g1 += w1.x * m10 + w1.y * m11 + w1.z * m12 + w1.w * m13;
            }
            // h part (Whh from L2)
            const float4* wh0 = (const float4*)(Whh + j0 * 128);
            const float4* wh1 = (const float4*)(Whh + j1 * 128);
#pragma unroll
            for (int kk = 0; kk < 32; ++kk) {
                const float4 w0 = wh0[kk], w1 = wh1[kk];
                const int k = kk * 4;
                const float h00 = sm[OFF_H + k],     h01 = sm[OFF_H + k + 1];
                const float h02 = sm[OFF_H + k + 2], h03 = sm[OFF_H + k + 3];
                const float h10 = sm[OFF_H + 128 + k],     h11 = sm[OFF_H + 128 + k + 1];
                const float h12 = sm[OFF_H + 128 + k + 2], h13 = sm[OFF_H + 128 + k + 3];
                a0g0 += w0.x * h00 + w0.y * h01 + w0.z * h02 + w0.w * h03;
                a0g1 += w0.x * h10 + w0.y * h11 + w0.z * h12 + w0.w * h13;
                a1g0 += w1.x * h00 + w1.y * h01 + w1.z * h02 + w1.w * h03;
                a1g1 += w1.x * h10 + w1.y * h11 + w1.z * h12 + w1.w * h13;
            }
            sm[OFF_GATES + j0]       = a0g0;
            sm[OFF_GATES + 512 + j0] = a0g1;
            sm[OFF_GATES + j1]       = a1g0;
            sm[OFF_GATES + 512 + j1] = a1g1;
        }
        __syncthreads();

        // ---- Phase G: LSTM update ----
        {
            const int g = t >> 7, j = t & 127;
            const float* gg = sm + OFF_GATES + g * 512;
            const float iv = sigf(gg[j]);
            const float fv = sigf(gg[128 + j]);
            const float gv = tanhf(gg[256 + j]);
            const float ov = sigf(gg[384 + j]);
            c_reg = fv * c_reg + iv * gv;
            sm[OFF_H + g * 128 + j] = ov * tanhf(c_reg);
        }
        __syncthreads();
    }

    // ---- deterministic per-block loss partial ----
    sm[OFF_RED + t] = loss_acc;
    __syncthreads();
    for (int off = 128; off > 0; off >>= 1) {
        if (t < off) sm[OFF_RED + t] += sm[OFF_RED + t + off];
        __syncthreads();
    }
    if (t == 0) g_lossPartial[blockIdx.x] = sm[OFF_RED];
}

__global__ void rits_loss_final(float* __restrict__ out, int out_size) {
    __shared__ float red[128];
    const int t = threadIdx.x;
    red[t] = g_lossPartial[t];
    __syncthreads();
    for (int off = 64; off > 0; off >>= 1) {
        if (t < off) red[t] += red[t + off];
        __syncthreads();
    }
    const long long bsf = (long long)Bdim * Sdim * Fdim;
    if (t == 0 && (long long)out_size > bsf) out[bsf] = red[0] / (float)Sdim;
}

extern "C" void kernel_launch(void* const* d_in, const int* in_sizes, int n_in,
                              void* d_out, int out_size) {
    const float* x   = (const float*)d_in[0];
    const float* m   = (const float*)d_in[1];
    const float* tt  = (const float*)d_in[2];
    const float* Wdh = (const float*)d_in[3];
    const float* bdh = (const float*)d_in[4];
    const float* Wdm = (const float*)d_in[5];
    const float* bdm = (const float*)d_in[6];
    const float* Wtr = (const float*)d_in[7];
    const float* btr = (const float*)d_in[8];
    const float* Wfr = (const float*)d_in[9];
    const float* bfr = (const float*)d_in[10];
    const float* Wwc = (const float*)d_in[11];
    const float* bwc = (const float*)d_in[12];
    const float* Wih = (const float*)d_in[13];
    const float* Whh = (const float*)d_in[14];
    const float* bih = (const float*)d_in[15];
    const float* bhh = (const float*)d_in[16];
    float* out = (float*)d_out;

    cudaFuncSetAttribute(rits_main_kernel,
                         cudaFuncAttributeMaxDynamicSharedMemorySize, SMEM_BYTES);

    rits_denom_kernel<<<Sdim, 256>>>(m);
    rits_main_kernel<<<Bdim / 2, 256, SMEM_BYTES>>>(
        x, m, tt, Wdh, bdh, Wdm, bdm, Wtr, btr, Wfr, bfr,
        Wwc, bwc, Wih, Whh, bih, bhh, out);
    rits_loss_final<<<1, 128>>>(out, out_size);
}

// round 3
// speedup vs baseline: 1.4271x; 1.4271x over previous
#include <cuda_runtime.h>

// RITS / BRITS-style recurrent imputation.
// B=256, S=512, F=64, H=128. fp32 throughout.
//
// Parallelization: batch rows are independent except for the scalar loss,
// whose per-step denominator depends only on input m (precomputed).
// One persistent block per 2 batch rows runs all 512 steps; loss partials
// are reduced deterministically at the end.

#define Bdim 256
#define Sdim 512
#define Fdim 64
#define Hdim 128
#define G4   512   // 4*H

// ---- scratch (no allocations allowed) ----
__device__ float g_invDenom[Sdim];
__device__ float g_lossPartial[Bdim / 2];

// ---- shared memory layout (floats) ----
// transposed weight tiles so inner-loop lanes are conflict-free
#define OFF_WTR   0                      // [128][64]  WtrT[k*64+f] = Wtr[f*H+k]
#define OFF_WFR   8192                   // [64][64]   WfrT[k*64+f] = Wfr_m[f][k]
#define OFF_WWC   12288                  // [128][64]  WwcT[k*64+f] = Wwc[f*128+k]
#define OFF_WIHX  20480                  // [64][512]  WihxT[k*512+j] = Wih[j*128+k]
#define OFF_BDH   53248                  // 128
#define OFF_BDM   53376                  // 64
#define OFF_BTR   53440                  // 64
#define OFF_BFR   53504                  // 64
#define OFF_BWC   53568                  // 64
#define OFF_BIO   53632                  // 512 (bih+bhh)
#define OFF_DWDM  54144                  // 64
#define OFF_XL    54208                  // [2][64]
#define OFF_ML    54336
#define OFF_TL    54464
#define OFF_GM    54592
#define OFF_XHAT  54720
#define OFF_XC    54848
#define OFF_ZHAT  54976
#define OFF_BETA  55104
#define OFF_CLC   55232
#define OFF_H     55360                  // [2][128]
#define OFF_GATES 55616                  // [2][512]
#define OFF_RED   56640                  // 256
#define SMEM_FLOATS 56896
#define SMEM_BYTES  (SMEM_FLOATS * 4)    // 227,584 B <= 232,448 opt-in cap

__device__ __forceinline__ float sigf(float v) { return 1.0f / (1.0f + expf(-v)); }

// Precompute per-step 1/(sum(m[:,s,:]) + 1e-5). One block per step, t = batch row.
__global__ void rits_denom_kernel(const float* __restrict__ m) {
    __shared__ float red[256];
    const int s = blockIdx.x;
    const int t = threadIdx.x;
    const float4* p = (const float4*)(m + (size_t)t * Sdim * Fdim + (size_t)s * Fdim);
    float sum = 0.f;
#pragma unroll
    for (int i = 0; i < 16; ++i) { float4 v = p[i]; sum += v.x + v.y + v.z + v.w; }
    red[t] = sum;
    __syncthreads();
    for (int off = 128; off > 0; off >>= 1) {
        if (t < off) red[t] += red[t + off];
        __syncthreads();
    }
    if (t == 0) g_invDenom[s] = 1.0f / (red[0] + 1e-5f);
}

__global__ __launch_bounds__(256, 1) void rits_main_kernel(
    const float* __restrict__ x,   const float* __restrict__ m,   const float* __restrict__ tt,
    const float* __restrict__ Wdh, const float* __restrict__ bdh,
    const float* __restrict__ Wdm, const float* __restrict__ bdm,
    const float* __restrict__ Wtr, const float* __restrict__ btr,
    const float* __restrict__ Wfr, const float* __restrict__ bfr,
    const float* __restrict__ Wwc, const float* __restrict__ bwc,
    const float* __restrict__ Wih, const float* __restrict__ Whh,
    const float* __restrict__ bih, const float* __restrict__ bhh,
    float* __restrict__ out)
{
    extern __shared__ float sm[];
    const int t  = threadIdx.x;
    const int b0 = blockIdx.x * 2;

    // ---- one-time weight staging (transposed into smem) ----
    for (int i = t; i < 8192; i += 256) { int k = i >> 6, f = i & 63; sm[OFF_WTR + i] = Wtr[f * Hdim + k]; }
    for (int i = t; i < 4096; i += 256) { int k = i >> 6, f = i & 63; sm[OFF_WFR + i] = (k == f) ? 0.f : Wfr[f * Fdim + k]; }
    for (int i = t; i < 8192; i += 256) { int k = i >> 6, f = i & 63; sm[OFF_WWC + i] = Wwc[f * 2 * Fdim + k]; }
    for (int i = t; i < 32768; i += 256) { int k = i >> 9, j = i & 511; sm[OFF_WIHX + i] = Wih[j * 2 * Fdim + k]; }
    if (t < 128) sm[OFF_BDH + t] = bdh[t];
    if (t < 64) {
        sm[OFF_BDM + t] = bdm[t];
        sm[OFF_BTR + t] = btr[t];
        sm[OFF_BFR + t] = bfr[t];
        sm[OFF_BWC + t] = bwc[t];
        sm[OFF_DWDM + t] = Wdm[t * Fdim + t];   // diagonal of Wdm
    }
    for (int i = t; i < 512; i += 256) sm[OFF_BIO + i] = bih[i] + bhh[i];
    sm[OFF_H + t] = 0.f;                        // h[2][128] zero
    float c_reg   = 0.f;                        // c for (g = t>>7, j = t&127)
    float loss_acc = 0.f;
    __syncthreads();

    for (int s = 0; s < Sdim; ++s) {
        // ---- Phase A: load x,m,t slice; gamma_m ----
        if (t < 128) {
            const int g = t >> 6, f = t & 63;
            const size_t idx = (size_t)(b0 + g) * Sdim * Fdim + (size_t)s * Fdim + f;
            const float xv = x[idx], mv = m[idx], tv = tt[idx];
            sm[OFF_XL + t] = xv;
            sm[OFF_ML + t] = mv;
            sm[OFF_TL + t] = tv;
            sm[OFF_GM + t] = expf(-fmaxf(tv * sm[OFF_DWDM + f] + sm[OFF_BDM + f], 0.f));
        }
        __syncthreads();

        // ---- Phase B: gamma_h, decay h (thread j handles both batch rows) ----
        if (t < 128) {
            const float4* wrow = (const float4*)(Wdh + t * Fdim);
            float a0 = 0.f, a1 = 0.f;
#pragma unroll
            for (int kk = 0; kk < 16; ++kk) {
                const float4 w = wrow[kk];
                const int k = kk * 4;
                a0 += w.x * sm[OFF_TL + k]     + w.y * sm[OFF_TL + k + 1]
                    + w.z * sm[OFF_TL + k + 2] + w.w * sm[OFF_TL + k + 3];
                a1 += w.x * sm[OFF_TL + 64 + k]     + w.y * sm[OFF_TL + 64 + k + 1]
                    + w.z * sm[OFF_TL + 64 + k + 2] + w.w * sm[OFF_TL + 64 + k + 3];
            }
            const float b = sm[OFF_BDH + t];
            sm[OFF_H + t]       *= expf(-fmaxf(a0 + b, 0.f));
            sm[OFF_H + 128 + t] *= expf(-fmaxf(a1 + b, 0.f));
        }
        __syncthreads();

        // ---- Phase C: xl_hat, xl_c ----
        if (t < 128) {
            const int g = t >> 6, f = t & 63;
            const float* hg = sm + OFF_H + g * 128;
            float a = sm[OFF_BTR + f];
#pragma unroll 8
            for (int k = 0; k < 128; ++k) a += hg[k] * sm[OFF_WTR + k * 64 + f];
            sm[OFF_XHAT + t] = a;
            const float mv = sm[OFF_ML + t];
            sm[OFF_XC + t] = mv * sm[OFF_XL + t] + (1.f - mv) * a;
        }
        __syncthreads();

        // ---- Phase D: zl_hat (threads 0..127) | beta (threads 128..255) ----
        if (t < 128) {
            const int g = t >> 6, f = t & 63;
            const float* xcg = sm + OFF_XC + g * 64;
            float a = sm[OFF_BFR + f];
#pragma unroll 8
            for (int k = 0; k < 64; ++k) a += xcg[k] * sm[OFF_WFR + k * 64 + f];
            sm[OFF_ZHAT + t] = a;
        } else {
            const int u = t - 128;
            const int g = u >> 6, f = u & 63;
            const float* gmg = sm + OFF_GM + g * 64;
            const float* mlg = sm + OFF_ML + g * 64;
            float a = sm[OFF_BWC + f];
#pragma unroll 8
            for (int k = 0; k < 64; ++k) {
                a += gmg[k] * sm[OFF_WWC + k * 64 + f];
                a += mlg[k] * sm[OFF_WWC + (64 + k) * 64 + f];
            }
            sm[OFF_BETA + u] = a;
        }
        __syncthreads();

        // ---- Phase E: cl_hat, cl_c, imputation write, loss ----
        if (t < 128) {
            const int g = t >> 6, f = t & 63;
            const float bt = sm[OFF_BETA + t], zh = sm[OFF_ZHAT + t];
            const float xh = sm[OFF_XHAT + t], mv = sm[OFF_ML + t], xv = sm[OFF_XL + t];
            const float ch = bt * zh + (1.f - bt) * xh;
            const float cc = mv * xv + (1.f - mv) * ch;
            sm[OFF_CLC + t] = cc;
            out[(size_t)(b0 + g) * Sdim * Fdim + (size_t)s * Fdim + f] = cc;
            const float d1 = xv - xh, d2 = xv - zh, d3 = xv - ch;
            loss_acc += mv * (d1 * d1 + d2 * d2 + d3 * d3) * g_invDenom[s];
        }
        __syncthreads();

        // ---- Phase F: gates = [cl_c, ml]@Wih^T + h@Whh^T + (bih+bhh) ----
        {
            const int j0 = t, j1 = t + 256;
            float a0g0 = sm[OFF_BIO + j0], a0g1 = a0g0;
            float a1g0 = sm[OFF_BIO + j1], a1g1 = a1g0;
            // cl_c half of Wih from smem
#pragma unroll 8
            for (int k = 0; k < 64; ++k) {
                const float c0 = sm[OFF_CLC + k], c1 = sm[OFF_CLC + 64 + k];
                const float w0 = sm[OFF_WIHX + k * 512 + j0];
                const float w1 = sm[OFF_WIHX + k * 512 + j1];
                a0g0 += w0 * c0; a0g1 += w0 * c1;
                a1g0 += w1 * c0; a1g1 += w1 * c1;
            }
            // mask half of Wih from L2
            const float4* w0p = (const float4*)(Wih + j0 * 128 + 64);
            const float4* w1p = (const float4*)(Wih + j1 * 128 + 64);
#pragma unroll
            for (int kk = 0; kk < 16; ++kk) {
                const float4 w0 = w0p[kk], w1 = w1p[kk];
                const int k = kk * 4;
                const float m00 = sm[OFF_ML + k],     m01 = sm[OFF_ML + k + 1];
                const float m02 = sm[OFF_ML + k + 2], m03 = sm[OFF_ML + k + 3];
                const float m10 = sm[OFF_ML + 64 + k],     m11 = sm[OFF_ML + 64 + k + 1];
                const float m12 = sm[OFF_ML + 64 + k + 2], m13 = sm[OFF_ML + 64 + k + 3];
                a0g0 += w0.x * m00 + w0.y * m01 + w0.z * m02 + w0.w * m03;
                a0g1 += w0.x * m10 + w0.y * m11 + w0.z * m12 + w0.w * m13;
                a1g0 += w1.x * m00 + w1.y * m01 + w1.z * m02 + w1.w * m03;
                a1g1 += w1.x * m10 + w1.y * m11 + w1.z * m12 + w1.w * m13;
            }
            // h part (Whh from L2)
            const float4* wh0 = (const float4*)(Whh + j0 * 128);
            const float4* wh1 = (const float4*)(Whh + j1 * 128);
#pragma unroll
            for (int kk = 0; kk < 32; ++kk) {
                const float4 w0 = wh0[kk], w1 = wh1[kk];
                const int k = kk * 4;
                const float h00 = sm[OFF_H + k],     h01 = sm[OFF_H + k + 1];
                const float h02 = sm[OFF_H + k + 2], h03 = sm[OFF_H + k + 3];
                const float h10 = sm[OFF_H + 128 + k],     h11 = sm[OFF_H + 128 + k + 1];
                const float h12 = sm[OFF_H + 128 + k + 2], h13 = sm[OFF_H + 128 + k + 3];
                a0g0 += w0.x * h00 + w0.y * h01 + w0.z * h02 + w0.w * h03;
                a0g1 += w0.x * h10 + w0.y * h11 + w0.z * h12 + w0.w * h13;
                a1g0 += w1.x * h00 + w1.y * h01 + w1.z * h02 + w1.w * h03;
                a1g1 += w1.x * h10 + w1.y * h11 + w1.z * h12 + w1.w * h13;
            }
            sm[OFF_GATES + j0]       = a0g0;
            sm[OFF_GATES + 512 + j0] = a0g1;
            sm[OFF_GATES + j1]       = a1g0;
            sm[OFF_GATES + 512 + j1] = a1g1;
        }
        __syncthreads();

        // ---- Phase G: LSTM update ----
        {
            const int g = t >> 7, j = t & 127;
            const float* gg = sm + OFF_GATES + g * 512;
            const float iv = sigf(gg[j]);
            const float fv = sigf(gg[128 + j]);
            const float gv = tanhf(gg[256 + j]);
            const float ov = sigf(gg[384 + j]);
            c_reg = fv * c_reg + iv * gv;
            sm[OFF_H + g * 128 + j] = ov * tanhf(c_reg);
        }
        __syncthreads();
    }

    // ---- deterministic per-block loss partial ----
    sm[OFF_RED + t] = loss_acc;
    __syncthreads();
    for (int off = 128; off > 0; off >>= 1) {
        if (t < off) sm[OFF_RED + t] += sm[OFF_RED + t + off];
        __syncthreads();
    }
    if (t == 0) g_lossPartial[blockIdx.x] = sm[OFF_RED];
}

__global__ void rits_loss_final(float* __restrict__ out, int out_size) {
    __shared__ float red[128];
    const int t = threadIdx.x;
    red[t] = g_lossPartial[t];
    __syncthreads();
    for (int off = 64; off > 0; off >>= 1) {
        if (t < off) red[t] += red[t + off];
        __syncthreads();
    }
    const long long bsf = (long long)Bdim * Sdim * Fdim;
    if (t == 0 && (long long)out_size > bsf) out[bsf] = red[0] / (float)Sdim;
}

extern "C" void kernel_launch(void* const* d_in, const int* in_sizes, int n_in,
                              void* d_out, int out_size) {
    const float* x   = (const float*)d_in[0];
    const float* m   = (const float*)d_in[1];
    const float* tt  = (const float*)d_in[2];
    const float* Wdh = (const float*)d_in[3];
    const float* bdh = (const float*)d_in[4];
    const float* Wdm = (const float*)d_in[5];
    const float* bdm = (const float*)d_in[6];
    const float* Wtr = (const float*)d_in[7];
    const float* btr = (const float*)d_in[8];
    const float* Wfr = (const float*)d_in[9];
    const float* bfr = (const float*)d_in[10];
    const float* Wwc = (const float*)d_in[11];
    const float* bwc = (const float*)d_in[12];
    const float* Wih = (const float*)d_in[13];
    const float* Whh = (const float*)d_in[14];
    const float* bih = (const float*)d_in[15];
    const float* bhh = (const float*)d_in[16];
    float* out = (float*)d_out;

    cudaFuncSetAttribute(rits_main_kernel,
                         cudaFuncAttributeMaxDynamicSharedMemorySize, SMEM_BYTES);

    rits_denom_kernel<<<Sdim, 256>>>(m);
    rits_main_kernel<<<Bdim / 2, 256, SMEM_BYTES>>>(
        x, m, tt, Wdh, bdh, Wdm, bdm, Wtr, btr, Wfr, bfr,
        Wwc, bwc, Wih, Whh, bih, bhh, out);
    rits_loss_final<<<1, 128>>>(out, out_size);
}

// round 4
// speedup vs baseline: 4.7681x; 3.3411x over previous
#include <cuda_runtime.h>

#define Bdim 256
#define Sdim 512
#define Fdim 64
#define Hdim 128
#define BS   (Bdim * Sdim)
#define NBLK 128
#define NRS  16            // Whh k-rows resident in smem
#define KQ   28            // streamed quad groups: k = 16..127

__device__ float g_invDenom[Sdim];
__device__ float g_lossPartial[NBLK];
__device__ float g_WhhQ[KQ * 512 * 4];              // [(q4*512+j)*4+r] = Whh[j][16+4q4+r]
__device__ float g_gh[(size_t)BS * Hdim];           // gamma_h
__device__ float g_beta[(size_t)BS * Fdim];         // beta
__device__ float g_gml[(size_t)(BS / 2) * 1024];    // pair-interleaved ml@WihMask^T + bio

typedef unsigned long long u64;
__device__ __forceinline__ u64 pk2(float lo, float hi) {
    u64 r; asm("mov.b64 %0,{%1,%2};" : "=l"(r) : "r"(__float_as_uint(lo)), "r"(__float_as_uint(hi))); return r;
}
__device__ __forceinline__ void up2(u64 v, float& lo, float& hi) {
    unsigned a, b; asm("mov.b64 {%0,%1},%2;" : "=r"(a), "=r"(b) : "l"(v));
    lo = __uint_as_float(a); hi = __uint_as_float(b);
}
__device__ __forceinline__ u64 ff2(u64 a, u64 b, u64 c) {
    u64 d; asm("fma.rn.f32x2 %0,%1,%2,%3;" : "=l"(d) : "l"(a), "l"(b), "l"(c)); return d;
}
__device__ __forceinline__ float sigf(float v) { return 1.f / (1.f + expf(-v)); }

// ---------- per-step 1/(sum(m)+1e-5) ----------
__global__ void rits_denom(const float* __restrict__ m) {
    __shared__ float red[256];
    const int s = blockIdx.x, t = threadIdx.x;
    const float4* p = (const float4*)(m + (size_t)t * Sdim * Fdim + (size_t)s * Fdim);
    float sum = 0.f;
#pragma unroll
    for (int i = 0; i < 16; ++i) { float4 v = p[i]; sum += v.x + v.y + v.z + v.w; }
    red[t] = sum;
    __syncthreads();
    for (int off = 128; off > 0; off >>= 1) { if (t < off) red[t] += red[t + off]; __syncthreads(); }
    if (t == 0) g_invDenom[s] = 1.0f / (red[0] + 1e-5f);
}

// ---------- Whh streamed-tail swizzle ----------
__global__ void rits_whhq(const float* __restrict__ Whh) {
    const int i = blockIdx.x * 256 + threadIdx.x;
    if (i < KQ * 512 * 4) {
        const int r = i & 3, j = (i >> 2) & 511, q4 = i >> 11;
        g_WhhQ[i] = Whh[j * Hdim + NRS + 4 * q4 + r];
    }
}

// ---------- gamma_h ----------
__global__ __launch_bounds__(256) void rits_gh(const float* __restrict__ tt,
                                               const float* __restrict__ Wdh,
                                               const float* __restrict__ bdh) {
    __shared__ float w[Fdim * Hdim];   // [k*128+h]
    __shared__ float bb[Hdim], tl[2 * Fdim];
    const int t = threadIdx.x;
    for (int i = t; i < Fdim * Hdim; i += 256) { const int k = i >> 7, h = i & 127; w[i] = Wdh[h * Fdim + k]; }
    if (t < Hdim) bb[t] = bdh[t];
    __syncthreads();
    const int rr = t >> 7, h = t & 127;
    const size_t base = (size_t)blockIdx.x * 256;
    for (int it = 0; it < 128; ++it) {
        const size_t rs = base + it * 2;
        if (t < 128) { const int rw = t >> 6, f = t & 63; tl[t] = tt[(rs + rw) * Fdim + f]; }
        __syncthreads();
        float a0 = 0.f, a1 = 0.f;
        const float* tlr = tl + rr * 64;
#pragma unroll 8
        for (int k = 0; k < Fdim; k += 2) { a0 += tlr[k] * w[k * 128 + h]; a1 += tlr[k + 1] * w[(k + 1) * 128 + h]; }
        g_gh[(rs + rr) * Hdim + h] = expf(-fmaxf(a0 + a1 + bb[h], 0.f));
        __syncthreads();
    }
}

// ---------- beta ----------
__global__ __launch_bounds__(256) void rits_betak(const float* __restrict__ tt, const float* __restrict__ m,
                                                  const float* __restrict__ Wdm, const float* __restrict__ bdm,
                                                  const float* __restrict__ Wwc, const float* __restrict__ bwc) {
    __shared__ float w[128 * Fdim];    // [k*64+f] = Wwc[f][k]
    __shared__ float dwdm[64], cb[64], cw[64], gm[4 * 64], ms[4 * 64];
    const int t = threadIdx.x;
    for (int i = t; i < 128 * Fdim; i += 256) { const int k = i >> 6, f = i & 63; w[i] = Wwc[f * 128 + k]; }
    if (t < 64) { dwdm[t] = Wdm[t * Fdim + t]; cb[t] = bdm[t]; cw[t] = bwc[t]; }
    __syncthreads();
    const int r = t >> 6, f = t & 63;
    const size_t base = (size_t)blockIdx.x * 256;
    for (int it = 0; it < 64; ++it) {
        const size_t rs = base + it * 4 + r;
        const float tv = tt[rs * Fdim + f], mv = m[rs * Fdim + f];
        gm[t] = expf(-fmaxf(tv * dwdm[f] + cb[f], 0.f)); ms[t] = mv;
        __syncthreads();
        float a0 = cw[f], a1 = 0.f;
        const float* gr = gm + r * 64; const float* mr = ms + r * 64;
#pragma unroll 8
        for (int k = 0; k < 64; ++k) { a0 += gr[k] * w[k * 64 + f]; a1 += mr[k] * w[(64 + k) * 64 + f]; }
        g_beta[rs * Fdim + f] = a0 + a1;
        __syncthreads();
    }
}

// ---------- gml = ml @ WihMask^T + bih + bhh (pair-interleaved) ----------
#define GML_SMF (32768 + 512 + 128)
__global__ __launch_bounds__(256, 1) void rits_gml(const float* __restrict__ m, const float* __restrict__ Wih,
                                                   const float* __restrict__ bih, const float* __restrict__ bhh) {
    extern __shared__ float sg[];
    float* WT  = sg;            // [(k2*512+j)*2+r] = Wih[j][64+2k2+r]
    float* BIO = sg + 32768;
    float* MLP = sg + 33280;    // [2f+g]
    const int t = threadIdx.x;
    for (int i = t; i < 32768; i += 256) { const int r = i & 1, j = (i >> 1) & 511, k2 = i >> 10; WT[i] = Wih[j * 128 + 64 + 2 * k2 + r]; }
    for (int i = t; i < 512; i += 256) BIO[i] = bih[i] + bhh[i];
    __syncthreads();
    const int j0 = t, j1 = t + 256;
    const size_t p0 = (size_t)blockIdx.x * 256;
    for (int it = 0; it < 256; ++it) {
        const size_t p = p0 + it, bp = p >> 9, s = p & 511;
        if (t < 128) { const int g = t >> 6, f = t & 63; MLP[2 * f + g] = m[((2 * bp + g) * Sdim + s) * Fdim + f]; }
        __syncthreads();
        u64 a0 = pk2(BIO[j0], BIO[j0]), a1 = pk2(BIO[j1], BIO[j1]);
#pragma unroll 8
        for (int k2 = 0; k2 < 32; ++k2) {
            const float4 q = *(const float4*)(MLP + 4 * k2);
            const u64 b0 = pk2(q.x, q.y), b1 = pk2(q.z, q.w);
            const float2 w0 = *(const float2*)(WT + (k2 * 512 + j0) * 2);
            const float2 w1 = *(const float2*)(WT + (k2 * 512 + j1) * 2);
            a0 = ff2(pk2(w0.x, w0.x), b0, a0); a0 = ff2(pk2(w0.y, w0.y), b1, a0);
            a1 = ff2(pk2(w1.x, w1.x), b0, a1); a1 = ff2(pk2(w1.y, w1.y), b1, a1);
        }
        *(u64*)(g_gml + p * 1024 + 2 * j0) = a0;
        *(u64*)(g_gml + p * 1024 + 2 * j1) = a1;
        __syncthreads();
    }
}

// ---------- main sequential kernel ----------
#define M_WIHC 0
#define M_WHH0 32768
#define M_WTRT 40960
#define M_WFRT 49152
#define M_BTR  53248
#define M_BFR  53312
#define M_XL   53376
#define M_ML   53504
#define M_HP   53632
#define M_XCP  53888
#define M_CLCP 54016
#define M_XH   54144
#define M_ZH   54272
#define M_GT   54400
#define M_RED  55424
#define M_SMF  55680
#define M_SMB  (M_SMF * 4)

__global__ __launch_bounds__(256, 1) void rits_main(
    const float* __restrict__ x, const float* __restrict__ m,
    const float* __restrict__ Wtr, const float* __restrict__ btr,
    const float* __restrict__ Wfr, const float* __restrict__ bfr,
    const float* __restrict__ Wih, const float* __restrict__ Whh,
    float* __restrict__ out)
{
    extern __shared__ float sm[];
    const int t = threadIdx.x;
    const int b0 = blockIdx.x * 2;

    for (int i = t; i < 32768; i += 256) { const int r = i & 1, j = (i >> 1) & 511, k2 = i >> 10; sm[M_WIHC + i] = Wih[j * 128 + 2 * k2 + r]; }
    for (int i = t; i < 8192; i += 256)  { const int r = i & 3, j = (i >> 2) & 511, k4 = i >> 11; sm[M_WHH0 + i] = Whh[j * 128 + 4 * k4 + r]; }
    for (int i = t; i < 8192; i += 256)  { const int r = i & 1, f = (i >> 1) & 63, k2 = i >> 7; sm[M_WTRT + i] = Wtr[f * 128 + 2 * k2 + r]; }
    for (int i = t; i < 4096; i += 256)  { const int r = i & 1, f = (i >> 1) & 63, k2 = i >> 7; const int k = 2 * k2 + r; sm[M_WFRT + i] = (k == f) ? 0.f : Wfr[f * 64 + k]; }
    if (t < 64) { sm[M_BTR + t] = btr[t]; sm[M_BFR + t] = bfr[t]; }
    sm[M_HP + t] = 0.f;
    float c_reg = 0.f, loss = 0.f;
    __syncthreads();

    const int gE = t >> 6, fE = t & 63;          // phases A/C/D/E (t<128)
    const int gG = t >> 7, jG = t & 127;         // phases AB-h, G
    const int j0 = t, j1 = t + 256;              // phase F
    const float* gmlBase = g_gml + (size_t)blockIdx.x * Sdim * 1024;

    for (int s = 0; s < Sdim; ++s) {
        // A: inputs   B: h *= gamma_h
        if (t < 128) {
            const size_t idx = ((size_t)(b0 + gE) * Sdim + s) * Fdim + fE;
            sm[M_XL + t] = x[idx]; sm[M_ML + t] = m[idx];
        }
        sm[M_HP + 2 * jG + gG] *= g_gh[((size_t)(b0 + gG) * Sdim + s) * Hdim + jG];
        __syncthreads();

        // C: xl_hat, xl_c
        if (t < 128) {
            const float* hg = sm + M_HP + gE;
            float a0 = 0.f, a1 = 0.f;
#pragma unroll 8
            for (int k2 = 0; k2 < 64; ++k2) {
                const float2 w = *(const float2*)(sm + M_WTRT + (k2 * 64 + fE) * 2);
                a0 += w.x * hg[4 * k2]; a1 += w.y * hg[4 * k2 + 2];
            }
            const float xh = sm[M_BTR + fE] + a0 + a1;
            sm[M_XH + t] = xh;
            const float mv = sm[M_ML + t];
            sm[M_XCP + 2 * fE + gE] = mv * sm[M_XL + t] + (1.f - mv) * xh;
        }
        __syncthreads();

        // D: zl_hat
        if (t < 128) {
            const float* xg = sm + M_XCP + gE;
            float a0 = 0.f, a1 = 0.f;
#pragma unroll 8
            for (int k2 = 0; k2 < 32; ++k2) {
                const float2 w = *(const float2*)(sm + M_WFRT + (k2 * 64 + fE) * 2);
                a0 += w.x * xg[4 * k2]; a1 += w.y * xg[4 * k2 + 2];
            }
            sm[M_ZH + t] = sm[M_BFR + fE] + a0 + a1;
        }
        __syncthreads();

        // E: cl_hat, cl_c, output, loss
        if (t < 128) {
            const size_t idx = ((size_t)(b0 + gE) * Sdim + s) * Fdim + fE;
            const float bt = g_beta[idx];
            const float xh = sm[M_XH + t], zh = sm[M_ZH + t];
            const float xv = sm[M_XL + t], mv = sm[M_ML + t];
            const float ch = bt * zh + (1.f - bt) * xh;
            const float cc = mv * xv + (1.f - mv) * ch;
            sm[M_CLCP + 2 * fE + gE] = cc;
            out[idx] = cc;
            const float d1 = xv - xh, d2 = xv - zh, d3 = xv - ch;
            loss += mv * (d1 * d1 + d2 * d2 + d3 * d3) * g_invDenom[s];
        }
        __syncthreads();

        // F: gates
        {
            const float* gp = gmlBase + (size_t)s * 1024;
            u64 a0 = *(const u64*)(gp + 2 * j0);
            u64 a1 = *(const u64*)(gp + 2 * j1);
#pragma unroll 8
            for (int k2 = 0; k2 < 32; ++k2) {
                const float4 q = *(const float4*)(sm + M_CLCP + 4 * k2);
                const u64 b0p = pk2(q.x, q.y), b1p = pk2(q.z, q.w);
                const float2 w0 = *(const float2*)(sm + M_WIHC + (k2 * 512 + j0) * 2);
                const float2 w1 = *(const float2*)(sm + M_WIHC + (k2 * 512 + j1) * 2);
                a0 = ff2(pk2(w0.x, w0.x), b0p, a0); a0 = ff2(pk2(w0.y, w0.y), b1p, a0);
                a1 = ff2(pk2(w1.x, w1.x), b0p, a1); a1 = ff2(pk2(w1.y, w1.y), b1p, a1);
            }
#pragma unroll
            for (int k4 = 0; k4 < 4; ++k4) {
                const float4 h01 = *(const float4*)(sm + M_HP + 8 * k4);
                const float4 h23 = *(const float4*)(sm + M_HP + 8 * k4 + 4);
                const u64 p0 = pk2(h01.x, h01.y), p1 = pk2(h01.z, h01.w);
                const u64 p2 = pk2(h23.x, h23.y), p3 = pk2(h23.z, h23.w);
                const float4 w0 = *(const float4*)(sm + M_WHH0 + (k4 * 512 + j0) * 4);
                const float4 w1 = *(const float4*)(sm + M_WHH0 + (k4 * 512 + j1) * 4);
                a0 = ff2(pk2(w0.x, w0.x), p0, a0); a0 = ff2(pk2(w0.y, w0.y), p1, a0);
                a0 = ff2(pk2(w0.z, w0.z), p2, a0); a0 = ff2(pk2(w0.w, w0.w), p3, a0);
                a1 = ff2(pk2(w1.x, w1.x), p0, a1); a1 = ff2(pk2(w1.y, w1.y), p1, a1);
                a1 = ff2(pk2(w1.z, w1.z), p2, a1); a1 = ff2(pk2(w1.w, w1.w), p3, a1);
            }
#pragma unroll 4
            for (int q4 = 0; q4 < KQ; ++q4) {
                const float4 w0 = *(const float4*)(g_WhhQ + ((size_t)q4 * 512 + j0) * 4);
                const float4 w1 = *(const float4*)(g_WhhQ + ((size_t)q4 * 512 + j1) * 4);
                const float4 h01 = *(const float4*)(sm + M_HP + 32 + 8 * q4);
                const float4 h23 = *(const float4*)(sm + M_HP + 36 + 8 * q4);
                const u64 p0 = pk2(h01.x, h01.y), p1 = pk2(h01.z, h01.w);
                const u64 p2 = pk2(h23.x, h23.y), p3 = pk2(h23.z, h23.w);
                a0 = ff2(pk2(w0.x, w0.x), p0, a0); a0 = ff2(pk2(w0.y, w0.y), p1, a0);
                a0 = ff2(pk2(w0.z, w0.z), p2, a0); a0 = ff2(pk2(w0.w, w0.w), p3, a0);
                a1 = ff2(pk2(w1.x, w1.x), p0, a1); a1 = ff2(pk2(w1.y, w1.y), p1, a1);
                a1 = ff2(pk2(w1.z, w1.z), p2, a1); a1 = ff2(pk2(w1.w, w1.w), p3, a1);
            }
            float v0, v1;
            up2(a0, v0, v1); sm[M_GT + j0] = v0; sm[M_GT + 512 + j0] = v1;
            up2(a1, v0, v1); sm[M_GT + j1] = v0; sm[M_GT + 512 + j1] = v1;
        }
        __syncthreads();

        // G: LSTM update
        {
            const float* gg = sm + M_GT + gG * 512;
            const float iv = sigf(gg[jG]);
            const float fv = sigf(gg[128 + jG]);
            const float gv = tanhf(gg[256 + jG]);
            const float ov = sigf(gg[384 + jG]);
            c_reg = fv * c_reg + iv * gv;
            sm[M_HP + 2 * jG + gG] = ov * tanhf(c_reg);
        }
        __syncthreads();
    }

    sm[M_RED + t] = loss;
    __syncthreads();
    for (int off = 128; off > 0; off >>= 1) { if (t < off) sm[M_RED + t] += sm[M_RED + t + off]; __syncthreads(); }
    if (t == 0) g_lossPartial[blockIdx.x] = sm[M_RED];
}

__global__ void rits_loss_final(float* __restrict__ out, int out_size) {
    __shared__ float red[NBLK];
    const int t = threadIdx.x;
    red[t] = g_lossPartial[t];
    __syncthreads();
    for (int off = 64; off > 0; off >>= 1) { if (t < off) red[t] += red[t + off]; __syncthreads(); }
    const long long bsf = (long long)Bdim * Sdim * Fdim;
    if (t == 0 && (long long)out_size > bsf) out[bsf] = red[0] / (float)Sdim;
}

extern "C" void kernel_launch(void* const* d_in, const int* in_sizes, int n_in,
                              void* d_out, int out_size) {
    const float* x   = (const float*)d_in[0];
    const float* m   = (const float*)d_in[1];
    const float* tt  = (const float*)d_in[2];
    const float* Wdh = (const float*)d_in[3];
    const float* bdh = (const float*)d_in[4];
    const float* Wdm = (const float*)d_in[5];
    const float* bdm = (const float*)d_in[6];
    const float* Wtr = (const float*)d_in[7];
    const float* btr = (const float*)d_in[8];
    const float* Wfr = (const float*)d_in[9];
    const float* bfr = (const float*)d_in[10];
    const float* Wwc = (const float*)d_in[11];
    const float* bwc = (const float*)d_in[12];
    const float* Wih = (const float*)d_in[13];
    const float* Whh = (const float*)d_in[14];
    const float* bih = (const float*)d_in[15];
    const float* bhh = (const float*)d_in[16];
    float* out = (float*)d_out;

    cudaFuncSetAttribute(rits_gml, cudaFuncAttributeMaxDynamicSharedMemorySize, GML_SMF * 4);
    cudaFuncSetAttribute(rits_main, cudaFuncAttributeMaxDynamicSharedMemorySize, M_SMB);

    rits_denom<<<Sdim, 256>>>(m);
    rits_whhq<<<(KQ * 512 * 4 + 255) / 256, 256>>>(Whh);
    rits_gh<<<512, 256>>>(tt, Wdh, bdh);
    rits_betak<<<512, 256>>>(tt, m, Wdm, bdm, Wwc, bwc);
    rits_gml<<<256, 256, GML_SMF * 4>>>(m, Wih, bih, bhh);
    rits_main<<<NBLK, 256, M_SMB>>>(x, m, Wtr, btr, Wfr, bfr, Wih, Whh, out);
    rits_loss_final<<<1, NBLK>>>(out, out_size);
}